// round 6
// baseline (speedup 1.0000x reference)
#include <cuda_runtime.h>
#include <cuda_bf16.h>

// FilterLayer: y[b,c,h,w] = sum_{di,dj in 5x5} x_zpad[b,c,h-2+di,w-2+dj] * f[b,di*5+dj,h,w]
// x: [4,3,512,512] f32, f: [4,25,512,512] f32, out: [4,3,512,512] f32
//
// HBM-bound streaming kernel: f (105 MB) read once, x staged in smem tile with halo.
// Block = 32x8 threads; each thread computes 4 horizontal pixels x 3 channels (float4).

#define IMG_H 512
#define IMG_W 512
#define NTAPS 25
#define NCH 3
#define TILE_W 128      // pixels per block in x (32 threads * 4 px)
#define TILE_H 8        // pixels per block in y
#define HALO 2
#define SROWS (TILE_H + 2*HALO)   // 12
#define SCOLS (TILE_W + 2*HALO)   // 132 valid columns
#define SSTRIDE 136               // row stride in floats: 544 B, 16B-aligned

__global__ __launch_bounds__(256) void filter_kernel(
    const float* __restrict__ x,
    const float* __restrict__ f,
    float* __restrict__ y)
{
    __shared__ __align__(16) float xs[NCH][SROWS][SSTRIDE];

    const int tx  = threadIdx.x;           // 0..31
    const int ty  = threadIdx.y;           // 0..7
    const int tid = ty * 32 + tx;
    const int b   = blockIdx.z;
    const int h0  = blockIdx.y * TILE_H;
    const int w0  = blockIdx.x * TILE_W;

    // ---- cooperative smem fill with zero padding at image borders ----
    const int FILL = NCH * SROWS * SCOLS;  // 3*12*132 = 4752
    #pragma unroll 5
    for (int idx = tid; idx < FILL; idx += 256) {
        int c   = idx / (SROWS * SCOLS);
        int r2  = idx - c * (SROWS * SCOLS);
        int row = r2 / SCOLS;
        int col = r2 - row * SCOLS;
        int gr  = h0 - HALO + row;
        int gc  = w0 - HALO + col;
        float v = 0.0f;
        if ((unsigned)gr < (unsigned)IMG_H && (unsigned)gc < (unsigned)IMG_W) {
            v = x[((((size_t)b * NCH + c) * IMG_H + gr) << 9) + gc];
        }
        xs[c][row][col] = v;
    }
    __syncthreads();

    const int h     = h0 + ty;
    const int wbase = w0 + tx * 4;

    float acc[NCH][4];
    #pragma unroll
    for (int c = 0; c < NCH; ++c)
        #pragma unroll
        for (int p = 0; p < 4; ++p)
            acc[c][p] = 0.0f;

    // f plane base: f[((b*25 + k)*512 + h)*512 + wbase]
    const float* fbase = f + (((size_t)b * NTAPS * IMG_H + h) << 9) + wbase;
    const size_t fplane = (size_t)IMG_H << 9;   // 512*512

    #pragma unroll
    for (int di = 0; di < 5; ++di) {
        // register window: 8 consecutive floats per channel, conflict-free LDS.128 x2
        float r[NCH][8];
        #pragma unroll
        for (int c = 0; c < NCH; ++c) {
            float4 a0 = *(const float4*)&xs[c][ty + di][tx * 4];
            float4 a1 = *(const float4*)&xs[c][ty + di][tx * 4 + 4];
            r[c][0] = a0.x; r[c][1] = a0.y; r[c][2] = a0.z; r[c][3] = a0.w;
            r[c][4] = a1.x; r[c][5] = a1.y; r[c][6] = a1.z; r[c][7] = a1.w;
        }
        #pragma unroll
        for (int dj = 0; dj < 5; ++dj) {
            const int k = di * 5 + dj;
            float4 fk = *(const float4*)(fbase + (size_t)k * fplane);
            #pragma unroll
            for (int c = 0; c < NCH; ++c) {
                acc[c][0] = fmaf(r[c][0 + dj], fk.x, acc[c][0]);
                acc[c][1] = fmaf(r[c][1 + dj], fk.y, acc[c][1]);
                acc[c][2] = fmaf(r[c][2 + dj], fk.z, acc[c][2]);
                acc[c][3] = fmaf(r[c][3 + dj], fk.w, acc[c][3]);
            }
        }
    }

    #pragma unroll
    for (int c = 0; c < NCH; ++c) {
        float4 o;
        o.x = acc[c][0]; o.y = acc[c][1]; o.z = acc[c][2]; o.w = acc[c][3];
        *(float4*)(y + ((((size_t)b * NCH + c) * IMG_H + h) << 9) + wbase) = o;
    }
}

extern "C" void kernel_launch(void* const* d_in, const int* in_sizes, int n_in,
                              void* d_out, int out_size) {
    const float* x = (const float*)d_in[0];   // [4,3,512,512]
    const float* f = (const float*)d_in[1];   // [4,25,512,512]
    // d_in[2] = window (5), compile-time constant here
    float* y = (float*)d_out;                 // [4,3,512,512]

    dim3 block(32, 8, 1);
    dim3 grid(IMG_W / TILE_W, IMG_H / TILE_H, 4);  // (4, 64, 4)
    filter_kernel<<<grid, block>>>(x, f, y);
}

// round 7
// speedup vs baseline: 1.1509x; 1.1509x over previous
#include <cuda_runtime.h>
#include <cuda_bf16.h>

// FilterLayer: y[b,c,h,w] = sum_{di,dj in 5x5} x_zpad[b,c,h-2+di,w-2+dj] * f[b,di*5+dj,h,w]
// x: [4,3,512,512] f32, f: [4,25,512,512] f32, out: [4,3,512,512] f32
//
// No-smem version: x staged through L1 with whole-vector predicated zero padding.
// Window [wbase-2, wbase+6) covered by 3 aligned float4 loads [wbase-4, wbase+8);
// since W=512 is a multiple of 4, each aligned float4 is fully in- or out-of-bounds,
// so vector-level predication implements exact ZeroPad2d semantics.
// Per di: 5 f-LDG.128 + 9 x-LDG.128 = 14 independent loads in flight (MLP up ~3x
// vs the smem version), no fill loop, no __syncthreads, no smem -> 4 CTAs/SM.

#define IMG_H 512
#define IMG_W 512
#define NTAPS 25
#define NCH 3

__global__ __launch_bounds__(256, 4) void filter_kernel(
    const float* __restrict__ x,
    const float* __restrict__ f,
    float* __restrict__ y)
{
    const int tx    = threadIdx.x;                 // 0..31
    const int ty    = threadIdx.y;                 // 0..7
    const int b     = blockIdx.z;
    const int h     = blockIdx.y * 8 + ty;         // uniform per warp
    const int wbase = blockIdx.x * 128 + tx * 4;

    const bool lok = (wbase >= 4);                 // left edge vector in-bounds
    const bool rok = (wbase <= IMG_W - 8);         // right edge vector in-bounds

    // f[b, k, h, wbase] ; planes at compile-time-constant strides from fbase
    const float* fbase = f + (((size_t)b * NTAPS * IMG_H + h) << 9) + wbase;
    const size_t fplane = (size_t)IMG_H << 9;      // 262144

    float acc[NCH][4];
    #pragma unroll
    for (int c = 0; c < NCH; ++c)
        #pragma unroll
        for (int p = 0; p < 4; ++p)
            acc[c][p] = 0.0f;

    #pragma unroll
    for (int di = 0; di < 5; ++di) {
        const int  gr    = h - 2 + di;
        const bool rowok = ((unsigned)gr < (unsigned)IMG_H);

        // Batch all 5 filter vectors for this tap-row (5 independent LDG.128)
        float4 fk[5];
        #pragma unroll
        for (int dj = 0; dj < 5; ++dj)
            fk[dj] = __ldg((const float4*)(fbase + (size_t)(di * 5 + dj) * fplane));

        #pragma unroll
        for (int c = 0; c < NCH; ++c) {
            const float* xr = x + ((((size_t)b * NCH + c) * IMG_H + gr) << 9);

            float4 L = make_float4(0.f, 0.f, 0.f, 0.f);
            float4 M = L;
            float4 R = L;
            if (rowok) {
                M = __ldg((const float4*)(xr + wbase));
                if (lok) L = __ldg((const float4*)(xr + wbase - 4));
                if (rok) R = __ldg((const float4*)(xr + wbase + 4));
            }
            // 12-float register window: cols [wbase-4, wbase+8)
            float r[12];
            r[0] = L.x; r[1]  = L.y; r[2]  = L.z; r[3]  = L.w;
            r[4] = M.x; r[5]  = M.y; r[6]  = M.z; r[7]  = M.w;
            r[8] = R.x; r[9]  = R.y; r[10] = R.z; r[11] = R.w;

            // pixel p, tap dj -> x col wbase + p + dj - 2 -> r[2 + p + dj]
            #pragma unroll
            for (int dj = 0; dj < 5; ++dj) {
                acc[c][0] = fmaf(r[2 + dj], fk[dj].x, acc[c][0]);
                acc[c][1] = fmaf(r[3 + dj], fk[dj].y, acc[c][1]);
                acc[c][2] = fmaf(r[4 + dj], fk[dj].z, acc[c][2]);
                acc[c][3] = fmaf(r[5 + dj], fk[dj].w, acc[c][3]);
            }
        }
    }

    #pragma unroll
    for (int c = 0; c < NCH; ++c) {
        float4 o;
        o.x = acc[c][0]; o.y = acc[c][1]; o.z = acc[c][2]; o.w = acc[c][3];
        *(float4*)(y + ((((size_t)b * NCH + c) * IMG_H + h) << 9) + wbase) = o;
    }
}

extern "C" void kernel_launch(void* const* d_in, const int* in_sizes, int n_in,
                              void* d_out, int out_size) {
    const float* x = (const float*)d_in[0];   // [4,3,512,512]
    const float* f = (const float*)d_in[1];   // [4,25,512,512]
    // d_in[2] = window (5), compile-time constant here
    float* y = (float*)d_out;                 // [4,3,512,512]

    dim3 block(32, 8, 1);
    dim3 grid(IMG_W / 128, IMG_H / 8, 4);     // (4, 64, 4) = 1024 CTAs
    filter_kernel<<<grid, block>>>(x, f, y);
}